// round 3
// baseline (speedup 1.0000x reference)
#include <cuda_runtime.h>
#include <math.h>

#define B_  8
#define H_  8
#define L_  1024
#define D_  64
#define DM_ 512
#define NC_ 5

// ---------------- scratch (__device__ globals; no allocation) ----------------
__device__ float g_G[B_*L_*15];        // G[bs][ll2][nc*3+t]
__device__ float g_q2[B_*L_*25];       // cluster_q2[bb][ll2][p*5+c]
__device__ float g_mu[B_*L_*NC_];      // mu[bb][ll2][j]
__device__ float g_kk[B_*H_*L_*D_];    // KK = sum_u2 cluster_center  (16MB)
__device__ float g_lp_sum;
__device__ float g_ce_sum;

__global__ void k_init() { g_lp_sum = 0.f; g_ce_sum = 0.f; }

// ---------------- kernel 1: G[bs,ll2,nc,t] = sum_c Kelem(bs,c,ll2)*w_k[nc,c,t]
// Kelem(bs,c,ll2) = K[bs, c>>6, (c&63)*16 + (ll2>>6), ll2&63]
// grid: B_*16 blocks (bs,g), 256 threads = (q in [0,64), cg in [0,4))
__global__ void k_gmat(const float* __restrict__ K, const float* __restrict__ wk) {
    int blk = blockIdx.x;
    int bs  = blk >> 4;
    int g   = blk & 15;
    int q   = threadIdx.x & 63;
    int cg  = threadIdx.x >> 6;

    __shared__ float wsh[NC_*DM_*3];   // 30KB
    for (int i = threadIdx.x; i < NC_*DM_*3; i += 256) wsh[i] = wk[i];
    __syncthreads();

    float acc[15];
    #pragma unroll
    for (int i = 0; i < 15; i++) acc[i] = 0.f;

    for (int c = cg*128; c < cg*128 + 128; c++) {
        int hh = c >> 6;
        int m  = c & 63;
        float kv = K[(((bs*H_ + hh)*L_) + m*16 + g)*D_ + q];
        const float* w = &wsh[c*3];     // element [nc][c][t] = nc*1536 + c*3 + t
        #pragma unroll
        for (int nc = 0; nc < 5; nc++)
            #pragma unroll
            for (int t = 0; t < 3; t++)
                acc[nc*3+t] += kv * w[nc*1536 + t];
    }

    __shared__ float red[4][64][15];   // 15KB
    #pragma unroll
    for (int i = 0; i < 15; i++) red[cg][q][i] = acc[i];
    __syncthreads();
    if (cg == 0) {
        int ll2 = g*64 + q;
        #pragma unroll
        for (int i = 0; i < 15; i++) {
            float s = red[0][q][i] + red[1][q][i] + red[2][q][i] + red[3][q][i];
            g_G[(bs*L_ + ll2)*15 + i] = s;
        }
    }
}

// ---------------- kernel 2: per-(bb,ll2) cluster math + loss partials --------
__global__ void k_small(const float* __restrict__ bk,
                        const float* __restrict__ wck, const float* __restrict__ bck,
                        const float* __restrict__ wcq, const float* __restrict__ bcq) {
    int idx = blockIdx.x*blockDim.x + threadIdx.x;   // exactly B_*L_ threads
    int bb = idx >> 10, ll = idx & 1023;

    // conv1x3 -> relu  : ckp[j][nc]
    // window source: K_padded[bb+jj] = K[bb+jj-4] only when bb+jj >= 5 (K[0] unused!)
    float ckp[5][5];
    #pragma unroll
    for (int j = 0; j < 5; j++)
        #pragma unroll
        for (int nc = 0; nc < 5; nc++) {
            float a = bk[nc];
            #pragma unroll
            for (int t = 0; t < 3; t++) {
                int jj = j + t - 1;
                if (jj >= 0 && jj < 5) {
                    int bs = bb + jj - 4;
                    if (bs >= 1) a += g_G[(bs*L_ + ll)*15 + nc*3 + t];
                }
            }
            ckp[j][nc] = fmaxf(a, 0.f);
        }

    float ck[5][5], cq[5][5];
    float lp_local = 0.f;
    #pragma unroll
    for (int j = 0; j < 5; j++) {
        float zk[5], zq[5];
        #pragma unroll
        for (int o = 0; o < 5; o++) {
            float sk = bck[o], sq = bcq[o];
            #pragma unroll
            for (int nc = 0; nc < 5; nc++) {
                sk += ckp[j][nc]*wck[o*5+nc];
                sq += ckp[j][nc]*wcq[o*5+nc];
            }
            zk[o] = sk; zq[o] = sq;
        }
        float mk = zk[0], mq = zq[0];
        #pragma unroll
        for (int o = 1; o < 5; o++) { mk = fmaxf(mk, zk[o]); mq = fmaxf(mq, zq[o]); }
        float sks = 0.f, sqs = 0.f;
        #pragma unroll
        for (int o = 0; o < 5; o++) {
            float ek = expf(zk[o]-mk), eq = expf(zq[o]-mq);
            ck[j][o] = ek; cq[j][o] = eq; sks += ek; sqs += eq;
        }
        float ik = 1.f/sks, iq = 1.f/sqs;
        #pragma unroll
        for (int o = 0; o < 5; o++) { ck[j][o] *= ik; cq[j][o] *= iq; }

        // stats / log_prob
        float mu = 0.f, x = 0.f;
        #pragma unroll
        for (int o = 0; o < 5; o++) { mu += cq[j][o]; x += ck[j][o]; }
        mu *= 0.2f; x *= 0.2f;
        float var = 0.f;
        #pragma unroll
        for (int o = 0; o < 5; o++) { float d = cq[j][o]-mu; var += d*d; }
        var *= 0.25f;                    // ddof=1 over 5
        float sd    = sqrtf(var);
        float sigma = logf(1.f + expf(sd));   // softplus
        float z     = (x - mu)/sigma;
        lp_local += -0.5f*z*z - logf(sigma) - 0.91893853320467274f;
        g_mu[idx*5 + j] = mu;
    }

    // masked 5x5 attention -> cluster_q2
    #pragma unroll
    for (int p = 0; p < 5; p++) {
        float sc[5];
        #pragma unroll
        for (int j = 0; j < 5; j++) {
            if (j > p) { sc[j] = -1e9f; continue; }
            float d = 0.f;
            #pragma unroll
            for (int c = 0; c < 5; c++) d += cq[p][c]*ck[j][c];
            sc[j] = d*0.2f;
        }
        float mx = sc[0];
        #pragma unroll
        for (int j = 1; j < 5; j++) mx = fmaxf(mx, sc[j]);
        float se = 0.f, ew[5];
        #pragma unroll
        for (int j = 0; j < 5; j++) { ew[j] = expf(sc[j]-mx); se += ew[j]; }
        float inv = 1.f/se;
        #pragma unroll
        for (int c = 0; c < 5; c++) {
            float v = 0.f;
            #pragma unroll
            for (int j = 0; j < 5; j++) v += ew[j]*cq[j][c];
            g_q2[idx*25 + p*5 + c] = v*inv;
        }
    }

    // reduce log_prob
    #pragma unroll
    for (int off = 16; off; off >>= 1)
        lp_local += __shfl_down_sync(0xffffffff, lp_local, off);
    if ((threadIdx.x & 31) == 0) atomicAdd(&g_lp_sum, lp_local);
}

// ---------------- kernel 3: KK[bb,hh,k,dd] = sum_u2 relu(conv_back) ----------
// reshape (b,512,l,5) -> (b,8,5,1024,64): flat_h = u2*65536 + k*64 + dd
//   c' = hh*64 + flat_h/5120, r = flat_h%5120, ll = r/5, j = r%5
__global__ void k_kk(const float* __restrict__ wpb, const float* __restrict__ bpb) {
    int idx = blockIdx.x*blockDim.x + threadIdx.x;
    if (idx >= B_*H_*L_*D_) return;
    int dd = idx & 63;
    int k  = (idx >> 6) & 1023;
    int hh = (idx >> 16) & 7;
    int bb = idx >> 19;
    const float* q2b = g_q2 + (bb << 10)*25;
    float acc = 0.f;
    #pragma unroll
    for (int u2 = 0; u2 < 5; u2++) {
        int fl = u2*65536 + (k << 6) + dd;
        int cp = fl / 5120;
        int r  = fl - cp*5120;
        int ll = r / 5;
        int j  = r - ll*5;
        int c  = (hh << 6) + cp;
        float v = bpb[c];
        const float* ql = q2b + ll*25;
        const float* w  = wpb + c*15;     // [c][nc][t] = c*15 + nc*3 + t
        #pragma unroll
        for (int t = 0; t < 3; t++) {
            int jj = j + t - 1;
            if (jj >= 0 && jj < 5) {
                #pragma unroll
                for (int nc = 0; nc < 5; nc++)
                    v += ql[jj*5 + nc]*w[nc*3 + t];
            }
        }
        acc += fmaxf(v, 0.f);
    }
    g_kk[idx] = acc;
}

// ---------------- kernel 4: CE term (log_softmax of mu over l) ---------------
__global__ void k_ce() {
    int bb = blockIdx.x / 5, j = blockIdx.x % 5;
    const float* base = g_mu + (bb << 10)*5 + j;
    __shared__ float sh[256];
    int tid = threadIdx.x;

    float mx = -1e30f;
    for (int ll = tid; ll < L_; ll += 256) mx = fmaxf(mx, base[ll*5]);
    sh[tid] = mx; __syncthreads();
    for (int s = 128; s > 0; s >>= 1) { if (tid < s) sh[tid] = fmaxf(sh[tid], sh[tid+s]); __syncthreads(); }
    mx = sh[0]; __syncthreads();

    float se = 0.f;
    for (int ll = tid; ll < L_; ll += 256) se += expf(base[ll*5] - mx);
    sh[tid] = se; __syncthreads();
    for (int s = 128; s > 0; s >>= 1) { if (tid < s) sh[tid] += sh[tid+s]; __syncthreads(); }
    float lse = mx + logf(sh[0]); __syncthreads();

    float acc = 0.f;
    for (int ll = tid; ll < L_; ll += 256) { float m = base[ll*5]; acc += m*(m - lse); }
    sh[tid] = acc; __syncthreads();
    for (int s = 128; s > 0; s >>= 1) { if (tid < s) sh[tid] += sh[tid+s]; __syncthreads(); }
    if (tid == 0) atomicAdd(&g_ce_sum, sh[0]);
}

__global__ void k_loss(float* out, int n) {
    out[n] = -(g_lp_sum / 40960.f) - (g_ce_sum / 40.f);
}

// ---------------- kernel 5: flash attention fp32 (1 thread = 1 q row) --------
__global__ void __launch_bounds__(128) k_attn(const float* __restrict__ Q,
                                              const float* __restrict__ V,
                                              float* __restrict__ out) {
    int blk = blockIdx.x;           // (bb*8+hh)*8 + qt
    int qt  = blk & 7;
    int bh  = blk >> 3;
    const float* Qb = Q    + (size_t)bh*L_*D_;
    const float* Kb = g_kk + (size_t)bh*L_*D_;
    const float* Vb = V    + (size_t)bh*L_*D_;
    float*       Ob = out  + (size_t)bh*L_*D_;
    int tid = threadIdx.x;

    __shared__ float qs[128][65];
    __shared__ float ks[32][64];
    __shared__ float vs[32][64];

    const float* Qt = Qb + qt*128*D_;
    for (int i = tid; i < 128*64/4; i += 128) {
        float4 v4 = ((const float4*)Qt)[i];
        int row = i >> 4, col = (i & 15)*4;
        qs[row][col] = v4.x; qs[row][col+1] = v4.y; qs[row][col+2] = v4.z; qs[row][col+3] = v4.w;
    }
    __syncthreads();

    float q[64], o[64];
    #pragma unroll
    for (int i = 0; i < 64; i++) { q[i] = qs[tid][i]; o[i] = 0.f; }
    float m = -1e30f, ssum = 0.f;

    for (int kt = 0; kt < L_; kt += 32) {
        __syncthreads();
        for (int i = tid; i < 32*64/4; i += 128) {
            ((float4*)&ks[0][0])[i] = ((const float4*)(Kb + kt*D_))[i];
            ((float4*)&vs[0][0])[i] = ((const float4*)(Vb + kt*D_))[i];
        }
        __syncthreads();

        for (int kk = 0; kk < 32; kk++) {
            float s0 = 0.f, s1 = 0.f, s2 = 0.f, s3 = 0.f;
            #pragma unroll
            for (int i = 0; i < 64; i += 4) {
                s0 += q[i]  *ks[kk][i];
                s1 += q[i+1]*ks[kk][i+1];
                s2 += q[i+2]*ks[kk][i+2];
                s3 += q[i+3]*ks[kk][i+3];
            }
            float s = (s0+s1) + (s2+s3);
            if (s > m) {                      // rare rescale path
                float corr = __expf(m - s);
                ssum *= corr;
                #pragma unroll
                for (int i = 0; i < 64; i++) o[i] *= corr;
                m = s;
            }
            float p = __expf(s - m);
            ssum += p;
            #pragma unroll
            for (int i = 0; i < 64; i++) o[i] += p*vs[kk][i];
        }
    }

    float inv = 1.f/ssum;
    float* orow = Ob + (qt*128 + tid)*D_;
    #pragma unroll
    for (int i = 0; i < 64; i += 4)
        ((float4*)orow)[i >> 2] = make_float4(o[i]*inv, o[i+1]*inv, o[i+2]*inv, o[i+3]*inv);
}

// ---------------- launcher ---------------------------------------------------
extern "C" void kernel_launch(void* const* d_in, const int* in_sizes, int n_in,
                              void* d_out, int out_size) {
    const float* Q   = (const float*)d_in[0];
    const float* K   = (const float*)d_in[1];
    const float* V   = (const float*)d_in[2];
    const float* wpk = (const float*)d_in[3];
    const float* bpk = (const float*)d_in[4];
    const float* wpb = (const float*)d_in[5];
    const float* bpb = (const float*)d_in[6];
    const float* wck = (const float*)d_in[7];
    const float* bck = (const float*)d_in[8];
    const float* wcq = (const float*)d_in[9];
    const float* bcq = (const float*)d_in[10];
    float* out = (float*)d_out;

    k_init<<<1, 1>>>();
    k_gmat<<<B_*16, 256>>>(K, wpk);
    k_small<<<(B_*L_)/256, 256>>>(bpk, wck, bck, wcq, bcq);
    k_kk<<<(B_*H_*L_*D_)/256, 256>>>(wpb, bpb);
    k_ce<<<B_*NC_, 256>>>();
    k_attn<<<B_*H_*8, 128>>>(Q, V, out);

    const int N = B_*H_*L_*D_;
    if (out_size > N) k_loss<<<1, 1>>>(out, N);
}

// round 4
// speedup vs baseline: 2.2564x; 2.2564x over previous
#include <cuda_runtime.h>
#include <cuda_fp16.h>
#include <math.h>
#include <stdint.h>

#define B_  8
#define H_  8
#define L_  1024
#define D_  64
#define DM_ 512
#define NC_ 5

// ---------------- scratch (__device__ globals; no allocation) ----------------
__device__ float g_G[B_*L_*15];        // G[bs][ll2][nc*3+t]
__device__ float g_q2[B_*L_*25];       // cluster_q2[bb][ll2][p*5+c]
__device__ float g_mu[B_*L_*NC_];      // mu[bb][ll2][j]
__device__ __half g_kh[B_*H_*L_*D_];   // KK split hi   [bh][key][dim]
__device__ __half g_kl[B_*H_*L_*D_];   // KK split lo
__device__ __half g_vh[B_*H_*D_*L_];   // V^T split hi  [bh][dim][key]
__device__ __half g_vl[B_*H_*D_*L_];   // V^T split lo
__device__ float g_lp_sum;
__device__ float g_ce_sum;

__global__ void k_init() { g_lp_sum = 0.f; g_ce_sum = 0.f; }

// ---------------- kernel 1: G[bs,ll2,nc,t] = sum_c Kelem(bs,c,ll2)*w_k[nc,c,t]
__global__ void k_gmat(const float* __restrict__ K, const float* __restrict__ wk) {
    int blk = blockIdx.x;
    int bs  = blk >> 4;
    int g   = blk & 15;
    int q   = threadIdx.x & 63;
    int cg  = threadIdx.x >> 6;

    __shared__ float wsh[NC_*DM_*3];
    for (int i = threadIdx.x; i < NC_*DM_*3; i += 256) wsh[i] = wk[i];
    __syncthreads();

    float acc[15];
    #pragma unroll
    for (int i = 0; i < 15; i++) acc[i] = 0.f;

    for (int c = cg*128; c < cg*128 + 128; c++) {
        int hh = c >> 6;
        int m  = c & 63;
        float kv = K[(((bs*H_ + hh)*L_) + m*16 + g)*D_ + q];
        #pragma unroll
        for (int nc = 0; nc < 5; nc++)
            #pragma unroll
            for (int t = 0; t < 3; t++)
                acc[nc*3+t] += kv * wsh[nc*1536 + c*3 + t];
    }

    __shared__ float red[4][64][15];
    #pragma unroll
    for (int i = 0; i < 15; i++) red[cg][q][i] = acc[i];
    __syncthreads();
    if (cg == 0) {
        int ll2 = g*64 + q;
        #pragma unroll
        for (int i = 0; i < 15; i++) {
            float s = red[0][q][i] + red[1][q][i] + red[2][q][i] + red[3][q][i];
            g_G[(bs*L_ + ll2)*15 + i] = s;
        }
    }
}

// ---------------- kernel 2: per-(bb,ll2) cluster math + loss partials --------
__global__ void k_small(const float* __restrict__ bk,
                        const float* __restrict__ wck, const float* __restrict__ bck,
                        const float* __restrict__ wcq, const float* __restrict__ bcq) {
    int idx = blockIdx.x*blockDim.x + threadIdx.x;
    int bb = idx >> 10, ll = idx & 1023;

    float ckp[5][5];
    #pragma unroll
    for (int j = 0; j < 5; j++)
        #pragma unroll
        for (int nc = 0; nc < 5; nc++) {
            float a = bk[nc];
            #pragma unroll
            for (int t = 0; t < 3; t++) {
                int jj = j + t - 1;
                if (jj >= 0 && jj < 5) {
                    int bs = bb + jj - 4;
                    if (bs >= 1) a += g_G[(bs*L_ + ll)*15 + nc*3 + t];
                }
            }
            ckp[j][nc] = fmaxf(a, 0.f);
        }

    float ck[5][5], cq[5][5];
    float lp_local = 0.f;
    #pragma unroll
    for (int j = 0; j < 5; j++) {
        float zk[5], zq[5];
        #pragma unroll
        for (int o = 0; o < 5; o++) {
            float sk = bck[o], sq = bcq[o];
            #pragma unroll
            for (int nc = 0; nc < 5; nc++) {
                sk += ckp[j][nc]*wck[o*5+nc];
                sq += ckp[j][nc]*wcq[o*5+nc];
            }
            zk[o] = sk; zq[o] = sq;
        }
        float mk = zk[0], mq = zq[0];
        #pragma unroll
        for (int o = 1; o < 5; o++) { mk = fmaxf(mk, zk[o]); mq = fmaxf(mq, zq[o]); }
        float sks = 0.f, sqs = 0.f;
        #pragma unroll
        for (int o = 0; o < 5; o++) {
            float ek = expf(zk[o]-mk), eq = expf(zq[o]-mq);
            ck[j][o] = ek; cq[j][o] = eq; sks += ek; sqs += eq;
        }
        float ik = 1.f/sks, iq = 1.f/sqs;
        #pragma unroll
        for (int o = 0; o < 5; o++) { ck[j][o] *= ik; cq[j][o] *= iq; }

        float mu = 0.f, x = 0.f;
        #pragma unroll
        for (int o = 0; o < 5; o++) { mu += cq[j][o]; x += ck[j][o]; }
        mu *= 0.2f; x *= 0.2f;
        float var = 0.f;
        #pragma unroll
        for (int o = 0; o < 5; o++) { float d = cq[j][o]-mu; var += d*d; }
        var *= 0.25f;
        float sd    = sqrtf(var);
        float sigma = logf(1.f + expf(sd));
        float z     = (x - mu)/sigma;
        lp_local += -0.5f*z*z - logf(sigma) - 0.91893853320467274f;
        g_mu[idx*5 + j] = mu;
    }

    #pragma unroll
    for (int p = 0; p < 5; p++) {
        float sc[5];
        #pragma unroll
        for (int j = 0; j < 5; j++) {
            if (j > p) { sc[j] = -1e9f; continue; }
            float d = 0.f;
            #pragma unroll
            for (int c = 0; c < 5; c++) d += cq[p][c]*ck[j][c];
            sc[j] = d*0.2f;
        }
        float mx = sc[0];
        #pragma unroll
        for (int j = 1; j < 5; j++) mx = fmaxf(mx, sc[j]);
        float se = 0.f, ew[5];
        #pragma unroll
        for (int j = 0; j < 5; j++) { ew[j] = expf(sc[j]-mx); se += ew[j]; }
        float inv = 1.f/se;
        #pragma unroll
        for (int c = 0; c < 5; c++) {
            float v = 0.f;
            #pragma unroll
            for (int j = 0; j < 5; j++) v += ew[j]*cq[j][c];
            g_q2[idx*25 + p*5 + c] = v*inv;
        }
    }

    #pragma unroll
    for (int off = 16; off; off >>= 1)
        lp_local += __shfl_down_sync(0xffffffff, lp_local, off);
    if ((threadIdx.x & 31) == 0) atomicAdd(&g_lp_sum, lp_local);
}

// ---------------- kernel 3: KK -> split fp16, divide-free index math ---------
// f = (hh*5+u2)*65536 + k*64 + dd is the flat512 index, and f = 5*(c*1024+ll)+j
__global__ void k_kk(const float* __restrict__ wpb, const float* __restrict__ bpb) {
    __shared__ float wsh[DM_*15];
    __shared__ float bsh[DM_];
    for (int i = threadIdx.x; i < DM_*15; i += 256) wsh[i] = wpb[i];
    for (int i = threadIdx.x; i < DM_;    i += 256) bsh[i] = bpb[i];
    __syncthreads();

    int idx = blockIdx.x*256 + threadIdx.x;
    int dd = idx & 63;
    int k  = (idx >> 6) & 1023;
    int hh = (idx >> 16) & 7;
    int bb = idx >> 19;
    const float* q2b = g_q2 + (bb << 10)*25;
    float acc = 0.f;
    #pragma unroll
    for (int u2 = 0; u2 < 5; u2++) {
        unsigned f  = ((unsigned)(hh*5 + u2) << 16) | (unsigned)((k << 6) | dd);
        unsigned s5 = f / 5u;                 // = c*1024 + ll
        int j  = (int)(f - s5*5u);
        int c  = (int)(s5 >> 10);
        int ll = (int)(s5 & 1023u);
        float v = bsh[c];
        const float* ql = q2b + ll*25;
        const float* w  = wsh + c*15;
        #pragma unroll
        for (int t = 0; t < 3; t++) {
            int jj = j + t - 1;
            if (jj >= 0 && jj < 5) {
                #pragma unroll
                for (int nc = 0; nc < 5; nc++)
                    v += ql[jj*5 + nc]*w[nc*3 + t];
            }
        }
        acc += fmaxf(v, 0.f);
    }
    __half h = __float2half_rn(acc);
    g_kh[idx] = h;
    g_kl[idx] = __float2half_rn(acc - __half2float(h));
}

// ---------------- kernel 3b: V -> transposed split fp16 ----------------------
__global__ void k_vprep(const float* __restrict__ V) {
    int bh = blockIdx.x >> 3, ch = blockIdx.x & 7;   // 128-key chunk
    const float* Vb = V + ((size_t)bh*L_ + ch*128)*D_;
    __shared__ float t[128][65];
    for (int i = threadIdx.x; i < 128*64/4; i += 256) {
        float4 v4 = ((const float4*)Vb)[i];
        int r = i >> 4, cl = (i & 15)*4;
        t[r][cl] = v4.x; t[r][cl+1] = v4.y; t[r][cl+2] = v4.z; t[r][cl+3] = v4.w;
    }
    __syncthreads();
    for (int i = threadIdx.x; i < 64*128; i += 256) {
        int d = i >> 7, key = i & 127;
        float v = t[key][d];
        __half h = __float2half_rn(v);
        size_t o = ((size_t)bh*64 + d)*1024 + ch*128 + key;
        g_vh[o] = h;
        g_vl[o] = __float2half_rn(v - __half2float(h));
    }
}

// ---------------- kernel 4: CE term ------------------------------------------
__global__ void k_ce() {
    int bb = blockIdx.x / 5, j = blockIdx.x % 5;
    const float* base = g_mu + (bb << 10)*5 + j;
    __shared__ float sh[256];
    int tid = threadIdx.x;

    float mx = -1e30f;
    for (int ll = tid; ll < L_; ll += 256) mx = fmaxf(mx, base[ll*5]);
    sh[tid] = mx; __syncthreads();
    for (int s = 128; s > 0; s >>= 1) { if (tid < s) sh[tid] = fmaxf(sh[tid], sh[tid+s]); __syncthreads(); }
    mx = sh[0]; __syncthreads();

    float se = 0.f;
    for (int ll = tid; ll < L_; ll += 256) se += expf(base[ll*5] - mx);
    sh[tid] = se; __syncthreads();
    for (int s = 128; s > 0; s >>= 1) { if (tid < s) sh[tid] += sh[tid+s]; __syncthreads(); }
    float lse = mx + logf(sh[0]); __syncthreads();

    float acc = 0.f;
    for (int ll = tid; ll < L_; ll += 256) { float m = base[ll*5]; acc += m*(m - lse); }
    sh[tid] = acc; __syncthreads();
    for (int s = 128; s > 0; s >>= 1) { if (tid < s) sh[tid] += sh[tid+s]; __syncthreads(); }
    if (tid == 0) atomicAdd(&g_ce_sum, sh[0]);
}

__global__ void k_loss(float* out, int n) {
    out[n] = -(g_lp_sum / 40960.f) - (g_ce_sum / 40.f);
}

// ---------------- kernel 5: flash attention, split-fp16 tensor-core ----------
__device__ __forceinline__ void mma16816(float d[4], const uint32_t a[4], const uint32_t b0, const uint32_t b1) {
    asm volatile("mma.sync.aligned.m16n8k16.row.col.f32.f16.f16.f32 "
                 "{%0,%1,%2,%3}, {%4,%5,%6,%7}, {%8,%9}, {%0,%1,%2,%3};\n"
                 : "+f"(d[0]), "+f"(d[1]), "+f"(d[2]), "+f"(d[3])
                 : "r"(a[0]), "r"(a[1]), "r"(a[2]), "r"(a[3]), "r"(b0), "r"(b1));
}
__device__ __forceinline__ uint32_t packh(__half x, __half y) {
    __half2 h = __halves2half2(x, y);
    return *reinterpret_cast<uint32_t*>(&h);
}
__device__ __forceinline__ void split2(float2 f, uint32_t& hi, uint32_t& lo) {
    __half hx = __float2half_rn(f.x), hy = __float2half_rn(f.y);
    __half lx = __float2half_rn(f.x - __half2float(hx));
    __half ly = __float2half_rn(f.y - __half2float(hy));
    hi = packh(hx, hy); lo = packh(lx, ly);
}

#define PADT 72   // halfs per smem tile row (144B: 16B-aligned, conflict-free frag loads)

__global__ void __launch_bounds__(256, 2) k_attn(const float* __restrict__ Q,
                                                 float* __restrict__ out) {
    int bh = blockIdx.x >> 3, qt = blockIdx.x & 7;
    int tid = threadIdx.x, w = tid >> 5, lane = tid & 31;
    int g = lane >> 2, c4 = lane & 3;

    __shared__ __half kh_s[64*PADT], kl_s[64*PADT], vh_s[64*PADT], vl_s[64*PADT];

    // preload this warp's Q fragments (16 rows x 64 dims), hi/lo split
    uint32_t qfh[4][4], qfl[4][4];
    const float* Qb = Q + ((size_t)bh*L_ + qt*128 + w*16)*D_;
    #pragma unroll
    for (int kc = 0; kc < 4; kc++) {
        int col0 = kc*16 + 2*c4;
        split2(*(const float2*)(Qb + g*D_      + col0),     qfh[kc][0], qfl[kc][0]);
        split2(*(const float2*)(Qb + (g+8)*D_  + col0),     qfh[kc][1], qfl[kc][1]);
        split2(*(const float2*)(Qb + g*D_      + col0 + 8), qfh[kc][2], qfl[kc][2]);
        split2(*(const float2*)(Qb + (g+8)*D_  + col0 + 8), qfh[kc][3], qfl[kc][3]);
    }

    float o[8][4];
    #pragma unroll
    for (int i = 0; i < 8; i++)
        #pragma unroll
        for (int e = 0; e < 4; e++) o[i][e] = 0.f;
    float m0 = -1e30f, m1 = -1e30f, l0 = 0.f, l1 = 0.f;

    const __half* khg = g_kh + (size_t)bh*L_*D_;
    const __half* klg = g_kl + (size_t)bh*L_*D_;
    const __half* vhg = g_vh + (size_t)bh*D_*L_;
    const __half* vlg = g_vl + (size_t)bh*D_*L_;

    for (int kt = 0; kt < 16; kt++) {
        __syncthreads();
        // stage 64-key tiles (K rows=keys; V rows=dims, cols=keys)
        for (int i = tid; i < 512; i += 256) {
            int r = i >> 3, ch = i & 7;
            ((uint4*)kh_s)[r*9 + ch] = ((const uint4*)(khg + kt*4096))[i];
            ((uint4*)kl_s)[r*9 + ch] = ((const uint4*)(klg + kt*4096))[i];
            ((uint4*)vh_s)[r*9 + ch] = ((const uint4*)(vhg + r*L_ + kt*64))[ch];
            ((uint4*)vl_s)[r*9 + ch] = ((const uint4*)(vlg + r*L_ + kt*64))[ch];
        }
        __syncthreads();

        #pragma unroll
        for (int hf = 0; hf < 2; hf++) {       // 32-key half-tiles
            float s[4][4];
            #pragma unroll
            for (int nt = 0; nt < 4; nt++)
                #pragma unroll
                for (int e = 0; e < 4; e++) s[nt][e] = 0.f;

            #pragma unroll
            for (int kc = 0; kc < 4; kc++) {
                #pragma unroll
                for (int nt = 0; nt < 4; nt++) {
                    int krow = hf*32 + nt*8 + g;
                    const __half* pb = kh_s + krow*PADT + kc*16 + 2*c4;
                    uint32_t bh0 = *(const uint32_t*)pb;
                    uint32_t bh1 = *(const uint32_t*)(pb + 8);
                    const __half* pl = kl_s + krow*PADT + kc*16 + 2*c4;
                    uint32_t bl0 = *(const uint32_t*)pl;
                    uint32_t bl1 = *(const uint32_t*)(pl + 8);
                    mma16816(s[nt], qfh[kc], bh0, bh1);
                    mma16816(s[nt], qfl[kc], bh0, bh1);
                    mma16816(s[nt], qfh[kc], bl0, bl1);
                }
            }

            // online softmax (rows g and g+8)
            float mt0 = s[0][0], mt1 = s[0][2];
            #pragma unroll
            for (int nt = 0; nt < 4; nt++) {
                mt0 = fmaxf(mt0, fmaxf(s[nt][0], s[nt][1]));
                mt1 = fmaxf(mt1, fmaxf(s[nt][2], s[nt][3]));
            }
            mt0 = fmaxf(mt0, __shfl_xor_sync(0xffffffff, mt0, 1));
            mt0 = fmaxf(mt0, __shfl_xor_sync(0xffffffff, mt0, 2));
            mt1 = fmaxf(mt1, __shfl_xor_sync(0xffffffff, mt1, 1));
            mt1 = fmaxf(mt1, __shfl_xor_sync(0xffffffff, mt1, 2));
            float m0n = fmaxf(m0, mt0), m1n = fmaxf(m1, mt1);
            float sc0 = __expf(m0 - m0n), sc1 = __expf(m1 - m1n);
            m0 = m0n; m1 = m1n;
            l0 *= sc0; l1 *= sc1;
            #pragma unroll
            for (int i = 0; i < 8; i++) {
                o[i][0] *= sc0; o[i][1] *= sc0;
                o[i][2] *= sc1; o[i][3] *= sc1;
            }

            uint32_t PH[4][2], PL[4][2];
            #pragma unroll
            for (int nt = 0; nt < 4; nt++) {
                float p0 = __expf(s[nt][0] - m0), p1 = __expf(s[nt][1] - m0);
                float p2 = __expf(s[nt][2] - m1), p3 = __expf(s[nt][3] - m1);
                l0 += p0 + p1; l1 += p2 + p3;
                __half h0 = __float2half_rn(p0), h1 = __float2half_rn(p1);
                __half h2 = __float2half_rn(p2), h3 = __float2half_rn(p3);
                PH[nt][0] = packh(h0, h1);
                PH[nt][1] = packh(h2, h3);
                PL[nt][0] = packh(__float2half_rn(p0 - __half2float(h0)),
                                  __float2half_rn(p1 - __half2float(h1)));
                PL[nt][1] = packh(__float2half_rn(p2 - __half2float(h2)),
                                  __float2half_rn(p3 - __half2float(h3)));
            }

            #pragma unroll
            for (int kc2 = 0; kc2 < 2; kc2++) {   // 16-key chunks
                uint32_t Ah[4] = {PH[2*kc2][0], PH[2*kc2][1], PH[2*kc2+1][0], PH[2*kc2+1][1]};
                uint32_t Al[4] = {PL[2*kc2][0], PL[2*kc2][1], PL[2*kc2+1][0], PL[2*kc2+1][1]};
                int colv = hf*32 + kc2*16 + 2*c4;
                #pragma unroll
                for (int nt = 0; nt < 8; nt++) {
                    int vrow = nt*8 + g;
                    const __half* pv = vh_s + vrow*PADT + colv;
                    uint32_t bv0 = *(const uint32_t*)pv;
                    uint32_t bv1 = *(const uint32_t*)(pv + 8);
                    const __half* pw = vl_s + vrow*PADT + colv;
                    uint32_t bw0 = *(const uint32_t*)pw;
                    uint32_t bw1 = *(const uint32_t*)(pw + 8);
                    mma16816(o[nt], Ah, bv0, bv1);
                    mma16816(o[nt], Al, bv0, bv1);
                    mma16816(o[nt], Ah, bw0, bw1);
                }
            }
        }
    }

    l0 += __shfl_xor_sync(0xffffffff, l0, 1);
    l0 += __shfl_xor_sync(0xffffffff, l0, 2);
    l1 += __shfl_xor_sync(0xffffffff, l1, 1);
    l1 += __shfl_xor_sync(0xffffffff, l1, 2);
    float inv0 = 1.f/l0, inv1 = 1.f/l1;

    float* Ob = out + ((size_t)bh*L_ + qt*128 + w*16)*D_;
    #pragma unroll
    for (int nt = 0; nt < 8; nt++) {
        int col = nt*8 + 2*c4;
        *(float2*)(Ob + g*D_     + col) = make_float2(o[nt][0]*inv0, o[nt][1]*inv0);
        *(float2*)(Ob + (g+8)*D_ + col) = make_float2(o[nt][2]*inv1, o[nt][3]*inv1);
    }
}

// ---------------- launcher ---------------------------------------------------
extern "C" void kernel_launch(void* const* d_in, const int* in_sizes, int n_in,
                              void* d_out, int out_size) {
    const float* Q   = (const float*)d_in[0];
    const float* K   = (const float*)d_in[1];
    const float* V   = (const float*)d_in[2];
    const float* wpk = (const float*)d_in[3];
    const float* bpk = (const float*)d_in[4];
    const float* wpb = (const float*)d_in[5];
    const float* bpb = (const float*)d_in[6];
    const float* wck = (const float*)d_in[7];
    const float* bck = (const float*)d_in[8];
    const float* wcq = (const float*)d_in[9];
    const float* bcq = (const float*)d_in[10];
    float* out = (float*)d_out;

    k_init<<<1, 1>>>();
    k_vprep<<<B_*H_*8, 256>>>(V);
    k_gmat<<<B_*16, 256>>>(K, wpk);
    k_small<<<(B_*L_)/256, 256>>>(bpk, wck, bck, wcq, bcq);
    k_kk<<<(B_*H_*L_*D_)/256, 256>>>(wpb, bpb);
    k_ce<<<B_*NC_, 256>>>();
    k_attn<<<B_*H_*8, 256>>>(Q, out);

    const int N = B_*H_*L_*D_;
    if (out_size > N) k_loss<<<1, 1>>>(out, N);
}

// round 5
// speedup vs baseline: 3.0312x; 1.3434x over previous
#include <cuda_runtime.h>
#include <cuda_fp16.h>
#include <math.h>
#include <stdint.h>

#define B_  8
#define H_  8
#define L_  1024
#define D_  64
#define DM_ 512
#define NC_ 5

// ---------------- scratch (__device__ globals; no allocation) ----------------
__device__ float g_G[B_*L_*15];        // G[bs][ll2][nc*3+t]
__device__ float g_q2[B_*L_*25];       // cluster_q2[bb][ll2][p*5+c]
__device__ float g_mu[B_*L_*NC_];      // mu[bb][ll2][j]
__device__ float g_r[B_*5*DM_*1024];   // relu(conv_back) at flat f  (84MB)
__device__ __half g_kh[B_*H_*L_*D_];   // KK split hi   [bh][key][dim]
__device__ __half g_kl[B_*H_*L_*D_];   // KK split lo
__device__ __half g_vh[B_*H_*D_*L_];   // V^T hi only   [bh][dim][key]
__device__ float g_lp_sum;
__device__ float g_ce_sum;

__global__ void k_init() { g_lp_sum = 0.f; g_ce_sum = 0.f; }

// ---------------- kernel 1: G[bs,ll2,nc,t] = sum_c Kelem(bs,c,ll2)*w_k[nc,c,t]
// 512 threads: q in [0,64), cg in [0,8) each covering 64 channels
__global__ void __launch_bounds__(512) k_gmat(const float* __restrict__ K,
                                              const float* __restrict__ wk) {
    int blk = blockIdx.x;
    int bs  = blk >> 4;
    int gg  = blk & 15;
    int q   = threadIdx.x & 63;
    int cg  = threadIdx.x >> 6;

    float acc[15];
    #pragma unroll
    for (int i = 0; i < 15; i++) acc[i] = 0.f;

    for (int c = cg*64; c < cg*64 + 64; c++) {
        int hh = c >> 6;
        int m  = c & 63;
        float kv = K[(((bs*H_ + hh)*L_) + m*16 + gg)*D_ + q];
        #pragma unroll
        for (int nc = 0; nc < 5; nc++)
            #pragma unroll
            for (int t = 0; t < 3; t++)
                acc[nc*3+t] += kv * __ldg(&wk[nc*1536 + c*3 + t]);
    }

    __shared__ float red[8][64][15];   // 30KB
    #pragma unroll
    for (int i = 0; i < 15; i++) red[cg][q][i] = acc[i];
    __syncthreads();
    if (cg == 0) {
        int ll2 = gg*64 + q;
        #pragma unroll
        for (int i = 0; i < 15; i++) {
            float s = 0.f;
            #pragma unroll
            for (int r = 0; r < 8; r++) s += red[r][q][i];
            g_G[(bs*L_ + ll2)*15 + i] = s;
        }
    }
}

// ---------------- kernel 2: per-(bb,ll2) cluster math + loss partials --------
__global__ void k_small(const float* __restrict__ bk,
                        const float* __restrict__ wck, const float* __restrict__ bck,
                        const float* __restrict__ wcq, const float* __restrict__ bcq) {
    int idx = blockIdx.x*blockDim.x + threadIdx.x;
    int bb = idx >> 10, ll = idx & 1023;

    float ckp[5][5];
    #pragma unroll
    for (int j = 0; j < 5; j++)
        #pragma unroll
        for (int nc = 0; nc < 5; nc++) {
            float a = bk[nc];
            #pragma unroll
            for (int t = 0; t < 3; t++) {
                int jj = j + t - 1;
                if (jj >= 0 && jj < 5) {
                    int bs = bb + jj - 4;
                    if (bs >= 1) a += g_G[(bs*L_ + ll)*15 + nc*3 + t];
                }
            }
            ckp[j][nc] = fmaxf(a, 0.f);
        }

    float ck[5][5], cq[5][5];
    float lp_local = 0.f;
    #pragma unroll
    for (int j = 0; j < 5; j++) {
        float zk[5], zq[5];
        #pragma unroll
        for (int o = 0; o < 5; o++) {
            float sk = bck[o], sq = bcq[o];
            #pragma unroll
            for (int nc = 0; nc < 5; nc++) {
                sk += ckp[j][nc]*wck[o*5+nc];
                sq += ckp[j][nc]*wcq[o*5+nc];
            }
            zk[o] = sk; zq[o] = sq;
        }
        float mk = zk[0], mq = zq[0];
        #pragma unroll
        for (int o = 1; o < 5; o++) { mk = fmaxf(mk, zk[o]); mq = fmaxf(mq, zq[o]); }
        float sks = 0.f, sqs = 0.f;
        #pragma unroll
        for (int o = 0; o < 5; o++) {
            float ek = expf(zk[o]-mk), eq = expf(zq[o]-mq);
            ck[j][o] = ek; cq[j][o] = eq; sks += ek; sqs += eq;
        }
        float ik = 1.f/sks, iq = 1.f/sqs;
        #pragma unroll
        for (int o = 0; o < 5; o++) { ck[j][o] *= ik; cq[j][o] *= iq; }

        float mu = 0.f, x = 0.f;
        #pragma unroll
        for (int o = 0; o < 5; o++) { mu += cq[j][o]; x += ck[j][o]; }
        mu *= 0.2f; x *= 0.2f;
        float var = 0.f;
        #pragma unroll
        for (int o = 0; o < 5; o++) { float d = cq[j][o]-mu; var += d*d; }
        var *= 0.25f;
        float sd    = sqrtf(var);
        float sigma = logf(1.f + expf(sd));
        float z     = (x - mu)/sigma;
        lp_local += -0.5f*z*z - logf(sigma) - 0.91893853320467274f;
        g_mu[idx*5 + j] = mu;
    }

    #pragma unroll
    for (int p = 0; p < 5; p++) {
        float sc[5];
        #pragma unroll
        for (int j = 0; j < 5; j++) {
            if (j > p) { sc[j] = -1e9f; continue; }
            float d = 0.f;
            #pragma unroll
            for (int c = 0; c < 5; c++) d += cq[p][c]*ck[j][c];
            sc[j] = d*0.2f;
        }
        float mx = sc[0];
        #pragma unroll
        for (int j = 1; j < 5; j++) mx = fmaxf(mx, sc[j]);
        float se = 0.f, ew[5];
        #pragma unroll
        for (int j = 0; j < 5; j++) { ew[j] = expf(sc[j]-mx); se += ew[j]; }
        float inv = 1.f/se;
        #pragma unroll
        for (int c = 0; c < 5; c++) {
            float v = 0.f;
            #pragma unroll
            for (int j = 0; j < 5; j++) v += ew[j]*cq[j][c];
            g_q2[idx*25 + p*5 + c] = v*inv;
        }
    }

    #pragma unroll
    for (int off = 16; off; off >>= 1)
        lp_local += __shfl_down_sync(0xffffffff, lp_local, off);
    if ((threadIdx.x & 31) == 0) atomicAdd(&g_lp_sum, lp_local);
}

// ---------------- kernel 3a: r[f] = relu(conv_back) with coalesced q2 reads --
// thread = (bb, c, ll); f = 5*(c*1024+ll)+j for j=0..4
__global__ void k_conv(const float* __restrict__ wpb, const float* __restrict__ bpb) {
    int blk = blockIdx.x;           // bb*512 + c
    int bb  = blk >> 9;
    int c   = blk & 511;
    float w[15];
    #pragma unroll
    for (int i = 0; i < 15; i++) w[i] = __ldg(&wpb[c*15 + i]);
    float bias = __ldg(&bpb[c]);

    float* rb = g_r + (size_t)bb*(5*DM_*1024) + (size_t)c*5120;
    const float* q2b = g_q2 + (bb << 10)*25;

    for (int ll = threadIdx.x; ll < 1024; ll += 256) {
        float q[25];
        #pragma unroll
        for (int i = 0; i < 25; i++) q[i] = q2b[ll*25 + i];
        #pragma unroll
        for (int j = 0; j < 5; j++) {
            float v = bias;
            #pragma unroll
            for (int t = 0; t < 3; t++) {
                int jj = j + t - 1;
                if (jj >= 0 && jj < 5) {
                    #pragma unroll
                    for (int nc = 0; nc < 5; nc++)
                        v += q[jj*5 + nc]*w[nc*3 + t];
                }
            }
            rb[ll*5 + j] = fmaxf(v, 0.f);
        }
    }
}

// ---------------- kernel 3b: KK[idx] = sum_u2 r[...] -> split fp16 -----------
__global__ void k_sum() {
    int idx = blockIdx.x*256 + threadIdx.x;    // bb,hh,pos
    int pos = idx & 65535;
    int hh  = (idx >> 16) & 7;
    int bb  = idx >> 19;
    const float* rb = g_r + (size_t)bb*(5*DM_*1024) + (size_t)(hh*5)*65536 + pos;
    float acc = rb[0] + rb[65536] + rb[2*65536] + rb[3*65536] + rb[4*65536];
    __half h = __float2half_rn(acc);
    g_kh[idx] = h;
    g_kl[idx] = __float2half_rn(acc - __half2float(h));
}

// ---------------- kernel 3c: V -> transposed fp16 (hi only) ------------------
__global__ void k_vprep(const float* __restrict__ V) {
    int bh = blockIdx.x >> 3, ch = blockIdx.x & 7;
    const float* Vb = V + ((size_t)bh*L_ + ch*128)*D_;
    __shared__ float t[128][65];
    for (int i = threadIdx.x; i < 128*64/4; i += 256) {
        float4 v4 = ((const float4*)Vb)[i];
        int r = i >> 4, cl = (i & 15)*4;
        t[r][cl] = v4.x; t[r][cl+1] = v4.y; t[r][cl+2] = v4.z; t[r][cl+3] = v4.w;
    }
    __syncthreads();
    for (int i = threadIdx.x; i < 64*128; i += 256) {
        int d = i >> 7, key = i & 127;
        g_vh[((size_t)bh*64 + d)*1024 + ch*128 + key] = __float2half_rn(t[key][d]);
    }
}

// ---------------- kernel 4: CE term ------------------------------------------
__global__ void k_ce() {
    int bb = blockIdx.x / 5, j = blockIdx.x % 5;
    const float* base = g_mu + (bb << 10)*5 + j;
    __shared__ float sh[256];
    int tid = threadIdx.x;

    float mx = -1e30f;
    for (int ll = tid; ll < L_; ll += 256) mx = fmaxf(mx, base[ll*5]);
    sh[tid] = mx; __syncthreads();
    for (int s = 128; s > 0; s >>= 1) { if (tid < s) sh[tid] = fmaxf(sh[tid], sh[tid+s]); __syncthreads(); }
    mx = sh[0]; __syncthreads();

    float se = 0.f;
    for (int ll = tid; ll < L_; ll += 256) se += expf(base[ll*5] - mx);
    sh[tid] = se; __syncthreads();
    for (int s = 128; s > 0; s >>= 1) { if (tid < s) sh[tid] += sh[tid+s]; __syncthreads(); }
    float lse = mx + logf(sh[0]); __syncthreads();

    float acc = 0.f;
    for (int ll = tid; ll < L_; ll += 256) { float m = base[ll*5]; acc += m*(m - lse); }
    sh[tid] = acc; __syncthreads();
    for (int s = 128; s > 0; s >>= 1) { if (tid < s) sh[tid] += sh[tid+s]; __syncthreads(); }
    if (tid == 0) atomicAdd(&g_ce_sum, sh[0]);
}

__global__ void k_loss(float* out, int n) {
    out[n] = -(g_lp_sum / 40960.f) - (g_ce_sum / 40.f);
}

// ---------------- kernel 5: flash attention, split-fp16 tensor-core ----------
__device__ __forceinline__ void mma16816(float d[4], const uint32_t a[4], const uint32_t b0, const uint32_t b1) {
    asm volatile("mma.sync.aligned.m16n8k16.row.col.f32.f16.f16.f32 "
                 "{%0,%1,%2,%3}, {%4,%5,%6,%7}, {%8,%9}, {%0,%1,%2,%3};\n"
                 : "+f"(d[0]), "+f"(d[1]), "+f"(d[2]), "+f"(d[3])
                 : "r"(a[0]), "r"(a[1]), "r"(a[2]), "r"(a[3]), "r"(b0), "r"(b1));
}
__device__ __forceinline__ uint32_t packh(__half x, __half y) {
    __half2 h = __halves2half2(x, y);
    return *reinterpret_cast<uint32_t*>(&h);
}
__device__ __forceinline__ void split2(float2 f, uint32_t& hi, uint32_t& lo) {
    __half hx = __float2half_rn(f.x), hy = __float2half_rn(f.y);
    __half lx = __float2half_rn(f.x - __half2float(hx));
    __half ly = __float2half_rn(f.y - __half2float(hy));
    hi = packh(hx, hy); lo = packh(lx, ly);
}
__device__ __forceinline__ void cpasync16(uint32_t smem_addr, const void* gptr) {
    asm volatile("cp.async.cg.shared.global [%0], [%1], 16;\n" :: "r"(smem_addr), "l"(gptr));
}

#define PADT 72          // halfs per smem row (144B)
#define TILE_H (64*PADT) // halfs per tile

// 128 threads; warp w handles q-rows [w*32, w*32+32) as 2 strips of 16
__global__ void __launch_bounds__(128, 2) k_attn(const float* __restrict__ Q,
                                                 float* __restrict__ out) {
    extern __shared__ __half sm[];
    int bh = blockIdx.x >> 3, qt = blockIdx.x & 7;
    int tid = threadIdx.x, w = tid >> 5, lane = tid & 31;
    int g = lane >> 2, c4 = lane & 3;

    const __half* khg = g_kh + (size_t)bh*L_*D_;
    const __half* klg = g_kl + (size_t)bh*L_*D_;
    const __half* vhg = g_vh + (size_t)bh*D_*L_;

    // Q fragments: 2 strips x 4 kc x 4, hi/lo
    uint32_t qfh[2][4][4], qfl[2][4][4];
    const float* Qb = Q + ((size_t)bh*L_ + qt*128 + w*32)*D_;
    #pragma unroll
    for (int st = 0; st < 2; st++)
        #pragma unroll
        for (int kc = 0; kc < 4; kc++) {
            int col0 = kc*16 + 2*c4;
            int r0 = st*16 + g, r1 = st*16 + g + 8;
            split2(*(const float2*)(Qb + r0*D_ + col0),     qfh[st][kc][0], qfl[st][kc][0]);
            split2(*(const float2*)(Qb + r1*D_ + col0),     qfh[st][kc][1], qfl[st][kc][1]);
            split2(*(const float2*)(Qb + r0*D_ + col0 + 8), qfh[st][kc][2], qfl[st][kc][2]);
            split2(*(const float2*)(Qb + r1*D_ + col0 + 8), qfh[st][kc][3], qfl[st][kc][3]);
        }

    float o[2][8][4];
    #pragma unroll
    for (int st = 0; st < 2; st++)
        #pragma unroll
        for (int i = 0; i < 8; i++)
            #pragma unroll
            for (int e = 0; e < 4; e++) o[st][i][e] = 0.f;
    float m[2][2] = {{-1e30f,-1e30f},{-1e30f,-1e30f}};
    float l[2][2] = {{0.f,0.f},{0.f,0.f}};

    uint32_t smbase = (uint32_t)__cvta_generic_to_shared(sm);

    // stage tile kt into buffer s (kh, kl, vh)
    auto stage = [&](int kt, int s) {
        uint32_t b = smbase + (uint32_t)s*(3*TILE_H*2);
        #pragma unroll
        for (int i = tid; i < 1536; i += 128) {
            int arr = i >> 9, j = i & 511;
            int r = j >> 3, ch = j & 7;
            const __half* src;
            if (arr == 0)      src = khg + kt*4096 + r*64 + ch*8;
            else if (arr == 1) src = klg + kt*4096 + r*64 + ch*8;
            else               src = vhg + r*1024 + kt*64 + ch*8;
            cpasync16(b + (uint32_t)arr*(TILE_H*2) + (uint32_t)(r*PADT + ch*8)*2, src);
        }
    };

    stage(0, 0);
    asm volatile("cp.async.commit_group;\n");

    for (int kt = 0; kt < 16; kt++) {
        int buf = kt & 1;
        if (kt < 15) stage(kt+1, buf ^ 1);
        asm volatile("cp.async.commit_group;\n");
        asm volatile("cp.async.wait_group 1;\n");
        __syncthreads();

        const __half* kh_s = sm + buf*(3*TILE_H);
        const __half* kl_s = kh_s + TILE_H;
        const __half* vh_s = kl_s + TILE_H;

        #pragma unroll
        for (int hf = 0; hf < 2; hf++) {
            float s[2][4][4];
            #pragma unroll
            for (int st = 0; st < 2; st++)
                #pragma unroll
                for (int nt = 0; nt < 4; nt++)
                    #pragma unroll
                    for (int e = 0; e < 4; e++) s[st][nt][e] = 0.f;

            #pragma unroll
            for (int kc = 0; kc < 4; kc++) {
                #pragma unroll
                for (int nt = 0; nt < 4; nt++) {
                    int krow = hf*32 + nt*8 + g;
                    const __half* pb = kh_s + krow*PADT + kc*16 + 2*c4;
                    uint32_t bh0 = *(const uint32_t*)pb;
                    uint32_t bh1 = *(const uint32_t*)(pb + 8);
                    const __half* pl = kl_s + krow*PADT + kc*16 + 2*c4;
                    uint32_t bl0 = *(const uint32_t*)pl;
                    uint32_t bl1 = *(const uint32_t*)(pl + 8);
                    #pragma unroll
                    for (int st = 0; st < 2; st++) {
                        mma16816(s[st][nt], qfh[st][kc], bh0, bh1);
                        mma16816(s[st][nt], qfl[st][kc], bh0, bh1);
                        mma16816(s[st][nt], qfh[st][kc], bl0, bl1);
                    }
                }
            }

            uint32_t PH[2][4][2], PL[2][4][2];
            #pragma unroll
            for (int st = 0; st < 2; st++) {
                float mt0 = s[st][0][0], mt1 = s[st][0][2];
                #pragma unroll
                for (int nt = 0; nt < 4; nt++) {
                    mt0 = fmaxf(mt0, fmaxf(s[st][nt][0], s[st][nt][1]));
                    mt1 = fmaxf(mt1, fmaxf(s[st][nt][2], s[st][nt][3]));
                }
                mt0 = fmaxf(mt0, __shfl_xor_sync(0xffffffff, mt0, 1));
                mt0 = fmaxf(mt0, __shfl_xor_sync(0xffffffff, mt0, 2));
                mt1 = fmaxf(mt1, __shfl_xor_sync(0xffffffff, mt1, 1));
                mt1 = fmaxf(mt1, __shfl_xor_sync(0xffffffff, mt1, 2));
                float m0n = fmaxf(m[st][0], mt0), m1n = fmaxf(m[st][1], mt1);
                float sc0 = __expf(m[st][0] - m0n), sc1 = __expf(m[st][1] - m1n);
                m[st][0] = m0n; m[st][1] = m1n;
                l[st][0] *= sc0; l[st][1] *= sc1;
                #pragma unroll
                for (int i = 0; i < 8; i++) {
                    o[st][i][0] *= sc0; o[st][i][1] *= sc0;
                    o[st][i][2] *= sc1; o[st][i][3] *= sc1;
                }
                #pragma unroll
                for (int nt = 0; nt < 4; nt++) {
                    float p0 = __expf(s[st][nt][0] - m0n), p1 = __expf(s[st][nt][1] - m0n);
                    float p2 = __expf(s[st][nt][2] - m1n), p3 = __expf(s[st][nt][3] - m1n);
                    l[st][0] += p0 + p1; l[st][1] += p2 + p3;
                    __half h0 = __float2half_rn(p0), h1 = __float2half_rn(p1);
                    __half h2 = __float2half_rn(p2), h3 = __float2half_rn(p3);
                    PH[st][nt][0] = packh(h0, h1);
                    PH[st][nt][1] = packh(h2, h3);
                    PL[st][nt][0] = packh(__float2half_rn(p0 - __half2float(h0)),
                                          __float2half_rn(p1 - __half2float(h1)));
                    PL[st][nt][1] = packh(__float2half_rn(p2 - __half2float(h2)),
                                          __float2half_rn(p3 - __half2float(h3)));
                }
            }

            #pragma unroll
            for (int kc2 = 0; kc2 < 2; kc2++) {
                int colv = hf*32 + kc2*16 + 2*c4;
                #pragma unroll
                for (int nt = 0; nt < 8; nt++) {
                    int vrow = nt*8 + g;
                    const __half* pv = vh_s + vrow*PADT + colv;
                    uint32_t bv0 = *(const uint32_t*)pv;
                    uint32_t bv1 = *(const uint32_t*)(pv + 8);
                    #pragma unroll
                    for (int st = 0; st < 2; st++) {
                        uint32_t Ah[4] = {PH[st][2*kc2][0], PH[st][2*kc2][1],
                                          PH[st][2*kc2+1][0], PH[st][2*kc2+1][1]};
                        uint32_t Al[4] = {PL[st][2*kc2][0], PL[st][2*kc2][1],
                                          PL[st][2*kc2+1][0], PL[st][2*kc2+1][1]};
                        mma16816(o[st][nt], Ah, bv0, bv1);
                        mma16816(o[st][nt], Al, bv0, bv1);
                    }
                }
            }
        }
        __syncthreads();   // all warps done with buf before it is overwritten
    }

    float* Ob = out + ((size_t)bh*L_ + qt*128 + w*32)*D_;
    #pragma unroll
    for (int st = 0; st < 2; st++) {
        float l0 = l[st][0], l1 = l[st][1];
        l0 += __shfl_xor_sync(0xffffffff, l0, 1);
        l0 += __shfl_xor_sync(0xffffffff, l0, 2);
        l1 += __shfl_xor_sync(0xffffffff, l1, 1);
        l1 += __shfl_xor_sync(0xffffffff, l1, 2);
        float inv0 = 1.f/l0, inv1 = 1.f/l1;
        #pragma unroll
        for (int nt = 0; nt < 8; nt++) {
            int col = nt*8 + 2*c4;
            *(float2*)(Ob + (st*16+g)*D_   + col) = make_float2(o[st][nt][0]*inv0, o[st][nt][1]*inv0);
            *(float2*)(Ob + (st*16+g+8)*D_ + col) = make_float2(o[st][nt][2]*inv1, o[st][nt][3]*inv1);
        }
    }
}

// ---------------- launcher ---------------------------------------------------
extern "C" void kernel_launch(void* const* d_in, const int* in_sizes, int n_in,
                              void* d_out, int out_size) {
    const float* Q   = (const float*)d_in[0];
    const float* K   = (const float*)d_in[1];
    const float* V   = (const float*)d_in[2];
    const float* wpk = (const float*)d_in[3];
    const float* bpk = (const float*)d_in[4];
    const float* wpb = (const float*)d_in[5];
    const float* bpb = (const float*)d_in[6];
    const float* wck = (const float*)d_in[7];
    const float* bck = (const float*)d_in[8];
    const float* wcq = (const float*)d_in[9];
    const float* bcq = (const float*)d_in[10];
    float* out = (float*)d_out;

    const int ATTN_SMEM = 2*3*TILE_H*2;   // 55296 B
    cudaFuncSetAttribute(k_attn, cudaFuncAttributeMaxDynamicSharedMemorySize, ATTN_SMEM);

    k_init<<<1, 1>>>();
    k_vprep<<<B_*H_*8, 256>>>(V);
    k_gmat<<<B_*16, 512>>>(K, wpk);
    k_small<<<(B_*L_)/64, 64>>>(bpk, wck, bck, wcq, bcq);
    k_conv<<<B_*DM_, 256>>>(wpb, bpb);
    k_sum<<<(B_*H_*L_*D_)/256, 256>>>();
    k_ce<<<B_*NC_, 256>>>();
    k_attn<<<B_*H_*8, 128, ATTN_SMEM>>>(Q, out);

    const int N = B_*H_*L_*D_;
    if (out_size > N) k_loss<<<1, 1>>>(out, N);
}

// round 6
// speedup vs baseline: 3.0705x; 1.0130x over previous
#include <cuda_runtime.h>
#include <cuda_fp16.h>
#include <math.h>
#include <stdint.h>

#define B_  8
#define H_  8
#define L_  1024
#define D_  64
#define DM_ 512
#define NC_ 5

// ---------------- scratch (__device__ globals; no allocation) ----------------
__device__ float g_G[B_*L_*15];        // G[bs][ll2][nc*3+t]
__device__ float g_q2[B_*L_*25];       // cluster_q2[bb][ll2][p*5+c]
__device__ float g_mu[B_*L_*NC_];      // mu[bb][ll2][j]
__device__ float g_r[B_*5*DM_*1024];   // relu(conv_back) at flat f  (84MB)
__device__ __half g_kh[B_*H_*L_*D_];   // KK split hi   [bh][key][dim]
__device__ __half g_kl[B_*H_*L_*D_];   // KK split lo
__device__ __half g_vh[B_*H_*D_*L_];   // V^T hi only   [bh][dim][key]
__device__ float g_lp_sum;
__device__ float g_ce_sum;

__global__ void k_init() { g_lp_sum = 0.f; g_ce_sum = 0.f; }

// ---------------- kernel 1: G[bs,ll2,nc,t] = sum_c Kelem(bs,c,ll2)*w_k[nc,c,t]
__global__ void __launch_bounds__(512) k_gmat(const float* __restrict__ K,
                                              const float* __restrict__ wk) {
    int blk = blockIdx.x;
    int bs  = blk >> 4;
    int gg  = blk & 15;
    int q   = threadIdx.x & 63;
    int cg  = threadIdx.x >> 6;

    float acc[15];
    #pragma unroll
    for (int i = 0; i < 15; i++) acc[i] = 0.f;

    for (int c = cg*64; c < cg*64 + 64; c++) {
        int hh = c >> 6;
        int m  = c & 63;
        float kv = K[(((bs*H_ + hh)*L_) + m*16 + gg)*D_ + q];
        #pragma unroll
        for (int nc = 0; nc < 5; nc++)
            #pragma unroll
            for (int t = 0; t < 3; t++)
                acc[nc*3+t] += kv * __ldg(&wk[nc*1536 + c*3 + t]);
    }

    __shared__ float red[8][64][15];
    #pragma unroll
    for (int i = 0; i < 15; i++) red[cg][q][i] = acc[i];
    __syncthreads();
    if (cg == 0) {
        int ll2 = gg*64 + q;
        #pragma unroll
        for (int i = 0; i < 15; i++) {
            float s = 0.f;
            #pragma unroll
            for (int r = 0; r < 8; r++) s += red[r][q][i];
            g_G[(bs*L_ + ll2)*15 + i] = s;
        }
    }
}

// ---------------- kernel 2: per-(bb,ll2) cluster math + loss partials --------
__global__ void k_small(const float* __restrict__ bk,
                        const float* __restrict__ wck, const float* __restrict__ bck,
                        const float* __restrict__ wcq, const float* __restrict__ bcq) {
    int idx = blockIdx.x*blockDim.x + threadIdx.x;
    int bb = idx >> 10, ll = idx & 1023;

    float ckp[5][5];
    #pragma unroll
    for (int j = 0; j < 5; j++)
        #pragma unroll
        for (int nc = 0; nc < 5; nc++) {
            float a = bk[nc];
            #pragma unroll
            for (int t = 0; t < 3; t++) {
                int jj = j + t - 1;
                if (jj >= 0 && jj < 5) {
                    int bs = bb + jj - 4;
                    if (bs >= 1) a += g_G[(bs*L_ + ll)*15 + nc*3 + t];
                }
            }
            ckp[j][nc] = fmaxf(a, 0.f);
        }

    float ck[5][5], cq[5][5];
    float lp_local = 0.f;
    #pragma unroll
    for (int j = 0; j < 5; j++) {
        float zk[5], zq[5];
        #pragma unroll
        for (int o = 0; o < 5; o++) {
            float sk = bck[o], sq = bcq[o];
            #pragma unroll
            for (int nc = 0; nc < 5; nc++) {
                sk += ckp[j][nc]*wck[o*5+nc];
                sq += ckp[j][nc]*wcq[o*5+nc];
            }
            zk[o] = sk; zq[o] = sq;
        }
        float mk = zk[0], mq = zq[0];
        #pragma unroll
        for (int o = 1; o < 5; o++) { mk = fmaxf(mk, zk[o]); mq = fmaxf(mq, zq[o]); }
        float sks = 0.f, sqs = 0.f;
        #pragma unroll
        for (int o = 0; o < 5; o++) {
            float ek = expf(zk[o]-mk), eq = expf(zq[o]-mq);
            ck[j][o] = ek; cq[j][o] = eq; sks += ek; sqs += eq;
        }
        float ik = 1.f/sks, iq = 1.f/sqs;
        #pragma unroll
        for (int o = 0; o < 5; o++) { ck[j][o] *= ik; cq[j][o] *= iq; }

        float mu = 0.f, x = 0.f;
        #pragma unroll
        for (int o = 0; o < 5; o++) { mu += cq[j][o]; x += ck[j][o]; }
        mu *= 0.2f; x *= 0.2f;
        float var = 0.f;
        #pragma unroll
        for (int o = 0; o < 5; o++) { float d = cq[j][o]-mu; var += d*d; }
        var *= 0.25f;
        float sd    = sqrtf(var);
        float sigma = logf(1.f + expf(sd));
        float z     = (x - mu)/sigma;
        lp_local += -0.5f*z*z - logf(sigma) - 0.91893853320467274f;
        g_mu[idx*5 + j] = mu;
    }

    #pragma unroll
    for (int p = 0; p < 5; p++) {
        float sc[5];
        #pragma unroll
        for (int j = 0; j < 5; j++) {
            if (j > p) { sc[j] = -1e9f; continue; }
            float d = 0.f;
            #pragma unroll
            for (int c = 0; c < 5; c++) d += cq[p][c]*ck[j][c];
            sc[j] = d*0.2f;
        }
        float mx = sc[0];
        #pragma unroll
        for (int j = 1; j < 5; j++) mx = fmaxf(mx, sc[j]);
        float se = 0.f, ew[5];
        #pragma unroll
        for (int j = 0; j < 5; j++) { ew[j] = expf(sc[j]-mx); se += ew[j]; }
        float inv = 1.f/se;
        #pragma unroll
        for (int c = 0; c < 5; c++) {
            float v = 0.f;
            #pragma unroll
            for (int j = 0; j < 5; j++) v += ew[j]*cq[j][c];
            g_q2[idx*25 + p*5 + c] = v*inv;
        }
    }

    #pragma unroll
    for (int off = 16; off; off >>= 1)
        lp_local += __shfl_down_sync(0xffffffff, lp_local, off);
    if ((threadIdx.x & 31) == 0) atomicAdd(&g_lp_sum, lp_local);
}

// ---------------- kernel 3a: r[f] = relu(conv_back), coalesced ---------------
__global__ void k_conv(const float* __restrict__ wpb, const float* __restrict__ bpb) {
    int blk = blockIdx.x;           // bb*512 + c
    int bb  = blk >> 9;
    int c   = blk & 511;
    float w[15];
    #pragma unroll
    for (int i = 0; i < 15; i++) w[i] = __ldg(&wpb[c*15 + i]);
    float bias = __ldg(&bpb[c]);

    float* rb = g_r + (size_t)bb*(5*DM_*1024) + (size_t)c*5120;
    const float* q2b = g_q2 + (bb << 10)*25;

    for (int ll = threadIdx.x; ll < 1024; ll += 256) {
        float q[25];
        #pragma unroll
        for (int i = 0; i < 25; i++) q[i] = q2b[ll*25 + i];
        #pragma unroll
        for (int j = 0; j < 5; j++) {
            float v = bias;
            #pragma unroll
            for (int t = 0; t < 3; t++) {
                int jj = j + t - 1;
                if (jj >= 0 && jj < 5) {
                    #pragma unroll
                    for (int nc = 0; nc < 5; nc++)
                        v += q[jj*5 + nc]*w[nc*3 + t];
                }
            }
            rb[ll*5 + j] = fmaxf(v, 0.f);
        }
    }
}

// ---------------- kernel 3b: KK[idx] = sum_u2 r[...] -> split fp16 -----------
__global__ void k_sum() {
    int idx = blockIdx.x*256 + threadIdx.x;
    int pos = idx & 65535;
    int hh  = (idx >> 16) & 7;
    int bb  = idx >> 19;
    const float* rb = g_r + (size_t)bb*(5*DM_*1024) + (size_t)(hh*5)*65536 + pos;
    float acc = rb[0] + rb[65536] + rb[2*65536] + rb[3*65536] + rb[4*65536];
    __half h = __float2half_rn(acc);
    g_kh[idx] = h;
    g_kl[idx] = __float2half_rn(acc - __half2float(h));
}

// ---------------- kernel 3c: V -> transposed fp16 (hi only) ------------------
__global__ void k_vprep(const float* __restrict__ V) {
    int bh = blockIdx.x >> 3, ch = blockIdx.x & 7;
    const float* Vb = V + ((size_t)bh*L_ + ch*128)*D_;
    __shared__ float t[128][65];
    for (int i = threadIdx.x; i < 128*64/4; i += 256) {
        float4 v4 = ((const float4*)Vb)[i];
        int r = i >> 4, cl = (i & 15)*4;
        t[r][cl] = v4.x; t[r][cl+1] = v4.y; t[r][cl+2] = v4.z; t[r][cl+3] = v4.w;
    }
    __syncthreads();
    for (int i = threadIdx.x; i < 64*128; i += 256) {
        int d = i >> 7, key = i & 127;
        g_vh[((size_t)bh*64 + d)*1024 + ch*128 + key] = __float2half_rn(t[key][d]);
    }
}

// ---------------- kernel 4: CE term ------------------------------------------
__global__ void k_ce() {
    int bb = blockIdx.x / 5, j = blockIdx.x % 5;
    const float* base = g_mu + (bb << 10)*5 + j;
    __shared__ float sh[256];
    int tid = threadIdx.x;

    float mx = -1e30f;
    for (int ll = tid; ll < L_; ll += 256) mx = fmaxf(mx, base[ll*5]);
    sh[tid] = mx; __syncthreads();
    for (int s = 128; s > 0; s >>= 1) { if (tid < s) sh[tid] = fmaxf(sh[tid], sh[tid+s]); __syncthreads(); }
    mx = sh[0]; __syncthreads();

    float se = 0.f;
    for (int ll = tid; ll < L_; ll += 256) se += expf(base[ll*5] - mx);
    sh[tid] = se; __syncthreads();
    for (int s = 128; s > 0; s >>= 1) { if (tid < s) sh[tid] += sh[tid+s]; __syncthreads(); }
    float lse = mx + logf(sh[0]); __syncthreads();

    float acc = 0.f;
    for (int ll = tid; ll < L_; ll += 256) { float m = base[ll*5]; acc += m*(m - lse); }
    sh[tid] = acc; __syncthreads();
    for (int s = 128; s > 0; s >>= 1) { if (tid < s) sh[tid] += sh[tid+s]; __syncthreads(); }
    if (tid == 0) atomicAdd(&g_ce_sum, sh[0]);
}

__global__ void k_loss(float* out, int n) {
    out[n] = -(g_lp_sum / 40960.f) - (g_ce_sum / 40.f);
}

// ---------------- kernel 5: flash attention, ldmatrix + split fp16 -----------
__device__ __forceinline__ void mma16816(float d[4], const uint32_t a[4], const uint32_t b0, const uint32_t b1) {
    asm volatile("mma.sync.aligned.m16n8k16.row.col.f32.f16.f16.f32 "
                 "{%0,%1,%2,%3}, {%4,%5,%6,%7}, {%8,%9}, {%0,%1,%2,%3};\n"
                 : "+f"(d[0]), "+f"(d[1]), "+f"(d[2]), "+f"(d[3])
                 : "r"(a[0]), "r"(a[1]), "r"(a[2]), "r"(a[3]), "r"(b0), "r"(b1));
}
__device__ __forceinline__ void ldm4(uint32_t r[4], uint32_t addr) {
    asm volatile("ldmatrix.sync.aligned.m8n8.x4.shared.b16 {%0,%1,%2,%3}, [%4];\n"
                 : "=r"(r[0]), "=r"(r[1]), "=r"(r[2]), "=r"(r[3]) : "r"(addr));
}
__device__ __forceinline__ uint32_t packh(__half x, __half y) {
    __half2 h = __halves2half2(x, y);
    return *reinterpret_cast<uint32_t*>(&h);
}
__device__ __forceinline__ void split2(float2 f, uint32_t& hi, uint32_t& lo) {
    __half hx = __float2half_rn(f.x), hy = __float2half_rn(f.y);
    __half lx = __float2half_rn(f.x - __half2float(hx));
    __half ly = __float2half_rn(f.y - __half2float(hy));
    hi = packh(hx, hy); lo = packh(lx, ly);
}
__device__ __forceinline__ float ex2(float x) {
    float y; asm("ex2.approx.f32 %0, %1;" : "=f"(y) : "f"(x)); return y;
}
__device__ __forceinline__ void cpasync16(uint32_t smem_addr, const void* gptr) {
    asm volatile("cp.async.cg.shared.global [%0], [%1], 16;\n" :: "r"(smem_addr), "l"(gptr));
}

#define PADT 72          // halfs per smem row (144B)
#define TILE_H (64*PADT) // halfs per tile array

// 256 threads, 8 warps; warp w owns q-rows [w*16, w*16+16)
__global__ void __launch_bounds__(256, 2) k_attn(const float* __restrict__ Q,
                                                 float* __restrict__ out) {
    extern __shared__ __half sm[];
    int bh = blockIdx.x >> 3, qt = blockIdx.x & 7;
    int tid = threadIdx.x, w = tid >> 5, lane = tid & 31;
    int g = lane >> 2, c4 = lane & 3;

    const __half* khg = g_kh + (size_t)bh*L_*D_;
    const __half* klg = g_kl + (size_t)bh*L_*D_;
    const __half* vhg = g_vh + (size_t)bh*D_*L_;

    // Q fragments, pre-scaled by log2(e) so softmax runs in exp2 domain
    const float LOG2E = 1.44269504088896340736f;
    uint32_t qfh[4][4], qfl[4][4];
    const float* Qb = Q + ((size_t)bh*L_ + qt*128 + w*16)*D_;
    #pragma unroll
    for (int kc = 0; kc < 4; kc++) {
        int col0 = kc*16 + 2*c4;
        float2 a0 = *(const float2*)(Qb + g*D_     + col0);
        float2 a1 = *(const float2*)(Qb + (g+8)*D_ + col0);
        float2 a2 = *(const float2*)(Qb + g*D_     + col0 + 8);
        float2 a3 = *(const float2*)(Qb + (g+8)*D_ + col0 + 8);
        a0.x *= LOG2E; a0.y *= LOG2E; a1.x *= LOG2E; a1.y *= LOG2E;
        a2.x *= LOG2E; a2.y *= LOG2E; a3.x *= LOG2E; a3.y *= LOG2E;
        split2(a0, qfh[kc][0], qfl[kc][0]);
        split2(a1, qfh[kc][1], qfl[kc][1]);
        split2(a2, qfh[kc][2], qfl[kc][2]);
        split2(a3, qfh[kc][3], qfl[kc][3]);
    }

    float o[8][4];
    #pragma unroll
    for (int i = 0; i < 8; i++)
        #pragma unroll
        for (int e = 0; e < 4; e++) o[i][e] = 0.f;
    float m0 = -1e30f, m1 = -1e30f, l0 = 0.f, l1 = 0.f;

    uint32_t smbase = (uint32_t)__cvta_generic_to_shared(sm);
    // per-lane ldmatrix row offset (same formula serves K and V tiles)
    int lrow = ((lane >> 4) << 3) + (lane & 7);
    uint32_t lsel = ((lane >> 3) & 1) << 3;
    uint32_t laneoff = (uint32_t)(lrow*PADT + lsel)*2;

    auto stage = [&](int kt, int s) {
        uint32_t b = smbase + (uint32_t)s*(3*TILE_H*2);
        #pragma unroll
        for (int i = tid; i < 1536; i += 256) {
            int arr = i >> 9, j = i & 511;
            int r = j >> 3, ch = j & 7;
            const __half* src;
            if (arr == 0)      src = khg + kt*4096 + r*64 + ch*8;
            else if (arr == 1) src = klg + kt*4096 + r*64 + ch*8;
            else               src = vhg + r*1024 + kt*64 + ch*8;
            cpasync16(b + (uint32_t)arr*(TILE_H*2) + (uint32_t)(r*PADT + ch*8)*2, src);
        }
    };

    stage(0, 0);
    asm volatile("cp.async.commit_group;\n");

    for (int kt = 0; kt < 16; kt++) {
        int buf = kt & 1;
        if (kt < 15) stage(kt+1, buf ^ 1);
        asm volatile("cp.async.commit_group;\n");
        asm volatile("cp.async.wait_group 1;\n");
        __syncthreads();

        uint32_t kh_b = smbase + (uint32_t)buf*(3*TILE_H*2) + laneoff;
        uint32_t kl_b = kh_b + TILE_H*2;
        uint32_t vh_b = kl_b + TILE_H*2;

        #pragma unroll
        for (int hf = 0; hf < 2; hf++) {
            float s[4][4];
            #pragma unroll
            for (int nt = 0; nt < 4; nt++)
                #pragma unroll
                for (int e = 0; e < 4; e++) s[nt][e] = 0.f;

            #pragma unroll
            for (int kc = 0; kc < 4; kc++) {
                #pragma unroll
                for (int np = 0; np < 2; np++) {
                    uint32_t off = (uint32_t)((hf*32 + np*16)*PADT + kc*16)*2;
                    uint32_t bhm[4], blm[4];
                    ldm4(bhm, kh_b + off);
                    ldm4(blm, kl_b + off);
                    mma16816(s[np*2],   qfh[kc], bhm[0], bhm[1]);
                    mma16816(s[np*2],   qfl[kc], bhm[0], bhm[1]);
                    mma16816(s[np*2],   qfh[kc], blm[0], blm[1]);
                    mma16816(s[np*2+1], qfh[kc], bhm[2], bhm[3]);
                    mma16816(s[np*2+1], qfl[kc], bhm[2], bhm[3]);
                    mma16816(s[np*2+1], qfh[kc], blm[2], blm[3]);
                }
            }

            // online softmax in exp2 domain (rows g, g+8)
            float mt0 = s[0][0], mt1 = s[0][2];
            #pragma unroll
            for (int nt = 0; nt < 4; nt++) {
                mt0 = fmaxf(mt0, fmaxf(s[nt][0], s[nt][1]));
                mt1 = fmaxf(mt1, fmaxf(s[nt][2], s[nt][3]));
            }
            mt0 = fmaxf(mt0, __shfl_xor_sync(0xffffffff, mt0, 1));
            mt0 = fmaxf(mt0, __shfl_xor_sync(0xffffffff, mt0, 2));
            mt1 = fmaxf(mt1, __shfl_xor_sync(0xffffffff, mt1, 1));
            mt1 = fmaxf(mt1, __shfl_xor_sync(0xffffffff, mt1, 2));
            float m0n = fmaxf(m0, mt0), m1n = fmaxf(m1, mt1);
            float sc0 = ex2(m0 - m0n), sc1 = ex2(m1 - m1n);
            m0 = m0n; m1 = m1n;
            l0 *= sc0; l1 *= sc1;
            #pragma unroll
            for (int i = 0; i < 8; i++) {
                o[i][0] *= sc0; o[i][1] *= sc0;
                o[i][2] *= sc1; o[i][3] *= sc1;
            }

            uint32_t PH[4][2], PL[4][2];
            #pragma unroll
            for (int nt = 0; nt < 4; nt++) {
                float p0 = ex2(s[nt][0] - m0), p1 = ex2(s[nt][1] - m0);
                float p2 = ex2(s[nt][2] - m1), p3 = ex2(s[nt][3] - m1);
                l0 += p0 + p1; l1 += p2 + p3;
                __half h0 = __float2half_rn(p0), h1 = __float2half_rn(p1);
                __half h2 = __float2half_rn(p2), h3 = __float2half_rn(p3);
                PH[nt][0] = packh(h0, h1);
                PH[nt][1] = packh(h2, h3);
                PL[nt][0] = packh(__float2half_rn(p0 - __half2float(h0)),
                                  __float2half_rn(p1 - __half2float(h1)));
                PL[nt][1] = packh(__float2half_rn(p2 - __half2float(h2)),
                                  __float2half_rn(p3 - __half2float(h3)));
            }

            #pragma unroll
            for (int kc2 = 0; kc2 < 2; kc2++) {
                uint32_t Ah[4] = {PH[2*kc2][0], PH[2*kc2][1], PH[2*kc2+1][0], PH[2*kc2+1][1]};
                uint32_t Al[4] = {PL[2*kc2][0], PL[2*kc2][1], PL[2*kc2+1][0], PL[2*kc2+1][1]};
                #pragma unroll
                for (int np = 0; np < 4; np++) {
                    uint32_t off = (uint32_t)(np*16*PADT + hf*32 + kc2*16)*2;
                    uint32_t bvm[4];
                    ldm4(bvm, vh_b + off);
                    mma16816(o[np*2],   Ah, bvm[0], bvm[1]);
                    mma16816(o[np*2],   Al, bvm[0], bvm[1]);
                    mma16816(o[np*2+1], Ah, bvm[2], bvm[3]);
                    mma16816(o[np*2+1], Al, bvm[2], bvm[3]);
                }
            }
        }
        __syncthreads();
    }

    l0 += __shfl_xor_sync(0xffffffff, l0, 1);
    l0 += __shfl_xor_sync(0xffffffff, l0, 2);
    l1 += __shfl_xor_sync(0xffffffff, l1, 1);
    l1 += __shfl_xor_sync(0xffffffff, l1, 2);
    float inv0 = 1.f/l0, inv1 = 1.f/l1;

    float* Ob = out + ((size_t)bh*L_ + qt*128 + w*16)*D_;
    #pragma unroll
    for (int nt = 0; nt < 8; nt++) {
        int col = nt*8 + 2*c4;
        *(float2*)(Ob + g*D_     + col) = make_float2(o[nt][0]*inv0, o[nt][1]*inv0);
        *(float2*)(Ob + (g+8)*D_ + col) = make_float2(o[nt][2]*inv1, o[nt][3]*inv1);
    }
}

// ---------------- launcher ---------------------------------------------------
extern "C" void kernel_launch(void* const* d_in, const int* in_sizes, int n_in,
                              void* d_out, int out_size) {
    const float* Q   = (const float*)d_in[0];
    const float* K   = (const float*)d_in[1];
    const float* V   = (const float*)d_in[2];
    const float* wpk = (const float*)d_in[3];
    const float* bpk = (const float*)d_in[4];
    const float* wpb = (const float*)d_in[5];
    const float* bpb = (const float*)d_in[6];
    const float* wck = (const float*)d_in[7];
    const float* bck = (const float*)d_in[8];
    const float* wcq = (const float*)d_in[9];
    const float* bcq = (const float*)d_in[10];
    float* out = (float*)d_out;

    const int ATTN_SMEM = 2*3*TILE_H*2;   // 55296 B
    cudaFuncSetAttribute(k_attn, cudaFuncAttributeMaxDynamicSharedMemorySize, ATTN_SMEM);

    k_init<<<1, 1>>>();
    k_vprep<<<B_*H_*8, 256>>>(V);
    k_gmat<<<B_*16, 512>>>(K, wpk);
    k_small<<<(B_*L_)/64, 64>>>(bpk, wck, bck, wcq, bcq);
    k_conv<<<B_*DM_, 256>>>(wpb, bpb);
    k_sum<<<(B_*H_*L_*D_)/256, 256>>>();
    k_ce<<<B_*NC_, 256>>>();
    k_attn<<<B_*H_*8, 256, ATTN_SMEM>>>(Q, out);

    const int N = B_*H_*L_*D_;
    if (out_size > N) k_loss<<<1, 1>>>(out, N);
}